// round 4
// baseline (speedup 1.0000x reference)
#include <cuda_runtime.h>
#include <cuda_fp16.h>
#include <cstdint>

// Problem constants
#define MM 8192
#define NN 8192
#define KK 4096
#define TM 128
#define TN 256
#define KS 64               // K elems per pipeline stage (128B rows)
#define STAGES 4
#define K_ITERS (KK / KS)   // 64

// Static scratch (allocation-free rule: __device__ globals): 64 MB + 64 MB
__device__ __half g_Ah[(size_t)MM * KK];
__device__ __half g_Wh[(size_t)NN * KK];

// ---------------------------------------------------------------------------
// Prep kernel 1: A (fp32, MxK) -> Ah (fp16, MxK). 8 elems/thread.
// ---------------------------------------------------------------------------
__global__ void prep_a_kernel(const float* __restrict__ A, __half* __restrict__ Ah) {
    size_t base = ((size_t)blockIdx.x * blockDim.x + threadIdx.x) * 8;
    float4 v0 = *reinterpret_cast<const float4*>(A + base);
    float4 v1 = *reinterpret_cast<const float4*>(A + base + 4);
    union { __half h[8]; uint4 u; } out;
    out.h[0] = __float2half(v0.x); out.h[1] = __float2half(v0.y);
    out.h[2] = __float2half(v0.z); out.h[3] = __float2half(v0.w);
    out.h[4] = __float2half(v1.x); out.h[5] = __float2half(v1.y);
    out.h[6] = __float2half(v1.z); out.h[7] = __float2half(v1.w);
    *reinterpret_cast<uint4*>(Ah + base) = out.u;
}

// ---------------------------------------------------------------------------
// Prep kernel 2: dequant int4 -> Wh (fp16, N x K), N-major rows.
// One thread = one n column x 64 k (8 packed words, all in one scale group).
// Reads coalesced across lanes; each thread stores 128B contiguous.
// ---------------------------------------------------------------------------
__global__ void prep_w_kernel(const int* __restrict__ Bp, const float* __restrict__ s,
                              __half* __restrict__ Wh) {
    int n   = blockIdx.x * 256 + threadIdx.x;
    int kp0 = blockIdx.y * 8;                         // 8 packed rows = 64 k
    float sv = s[(size_t)(kp0 >> 4) * NN + n];        // group = kp/16, same for all 8
    __half* dst = Wh + (size_t)n * KK + kp0 * 8;
#pragma unroll
    for (int r = 0; r < 8; r++) {
        int packed = Bp[(size_t)(kp0 + r) * NN + n];
        union { __half h[8]; uint4 u; } out;
#pragma unroll
        for (int j = 0; j < 8; j++) {
            int q = (packed >> (4 * j)) & 0xF;
            out.h[j] = __float2half((float)(q - 8) * sv);
        }
        *reinterpret_cast<uint4*>(dst + r * 8) = out.u;
    }
}

// ---------------------------------------------------------------------------
// GEMM: C[M,N] = Ah @ Wh^T (fp16 in, f32 acc)
// CTA 128x256, 8 warps (2m x 4n), warp tile 64x64, mma.sync.m16n8k16.
// 4-stage cp.async pipeline, KS=64; chunk swizzle c^(row&7).
// kt-level fragment double-buffering: prefetch kt+1 LDSMs before kt MMAs.
// ---------------------------------------------------------------------------
#define A_STAGE_BYTES 16384              // 128 x 64 x 2
#define B_STAGE_BYTES 32768              // 256 x 64 x 2
#define SMEM_BYTES (STAGES * (A_STAGE_BYTES + B_STAGE_BYTES))   // 196608

__device__ __forceinline__ uint32_t smem_u32(const void* p) {
    uint32_t a;
    asm("{ .reg .u64 t; cvta.to.shared.u64 t, %1; cvt.u32.u64 %0, t; }" : "=r"(a) : "l"(p));
    return a;
}

#define CP_ASYNC16(smem, gmem) \
    asm volatile("cp.async.cg.shared.global [%0], [%1], 16;" :: "r"(smem), "l"(gmem))
#define CP_COMMIT() asm volatile("cp.async.commit_group;" ::: "memory")
#define CP_WAIT2()  asm volatile("cp.async.wait_group 2;" ::: "memory")

#define LDSM_X4(r, addr) \
    asm volatile("ldmatrix.sync.aligned.m8n8.x4.shared.b16 {%0,%1,%2,%3}, [%4];" \
        : "=r"((r)[0]), "=r"((r)[1]), "=r"((r)[2]), "=r"((r)[3]) : "r"(addr))

#define MMA16816(d, a, b0, b1) \
    asm volatile("mma.sync.aligned.m16n8k16.row.col.f32.f16.f16.f32 " \
        "{%0,%1,%2,%3}, {%4,%5,%6,%7}, {%8,%9}, {%0,%1,%2,%3};" \
        : "+f"((d)[0]), "+f"((d)[1]), "+f"((d)[2]), "+f"((d)[3]) \
        : "r"((a)[0]), "r"((a)[1]), "r"((a)[2]), "r"((a)[3]), "r"(b0), "r"(b1))

__global__ __launch_bounds__(256, 1) void gemm_kernel(
    const __half* __restrict__ gA,
    const __half* __restrict__ gB,
    float* __restrict__ C)
{
    extern __shared__ char smem[];
    const uint32_t sbase = smem_u32(smem);
    const int tid = threadIdx.x, wid = tid >> 5, lid = tid & 31;

    // CTA swizzle: 8-wide m-bands sweeping n (L2 reuse)
    const int TILES_N = NN / TN;        // 32
    const int GW = 8;
    int bid  = blockIdx.x;
    int band = bid / (GW * TILES_N);
    int rem  = bid % (GW * TILES_N);
    const int m0 = (band * GW + (rem % GW)) * TM;
    const int n0 = (rem / GW) * TN;

    const int warpM = (wid & 1) * 64;   // 2 m-warps
    const int warpN = (wid >> 1) * 64;  // 4 n-warps

    auto stage_load = [&](int st, int it) {
        const int k0 = it * KS;
        const uint32_t sa = sbase + st * A_STAGE_BYTES;
        const uint32_t sb = sbase + STAGES * A_STAGE_BYTES + st * B_STAGE_BYTES;
        const int c = tid & 7;
#pragma unroll
        for (int r = 0; r < 4; r++) {                // A: 1024 chunks
            int row = (tid + r * 256) >> 3;
            uint32_t soff = row * 128 + ((c ^ (row & 7)) << 4);
            CP_ASYNC16(sa + soff, gA + (size_t)(m0 + row) * KK + k0 + c * 8);
        }
#pragma unroll
        for (int r = 0; r < 8; r++) {                // B: 2048 chunks
            int row = (tid + r * 256) >> 3;
            uint32_t soff = row * 128 + ((c ^ (row & 7)) << 4);
            CP_ASYNC16(sb + soff, gB + (size_t)(n0 + row) * KK + k0 + c * 8);
        }
    };

    // Prologue: fill STAGES-1 stages
#pragma unroll
    for (int p = 0; p < STAGES - 1; p++) {
        stage_load(p, p);
        CP_COMMIT();
    }

    float acc[4][8][4];
#pragma unroll
    for (int mi = 0; mi < 4; mi++)
#pragma unroll
        for (int ni = 0; ni < 8; ni++)
#pragma unroll
            for (int v = 0; v < 4; v++) acc[mi][ni][v] = 0.f;

    const int lrow  = lid & 15;          // row within 16-row subtile
    const int lhalf = lid >> 4;          // k-chunk half (0/1)
    const int lsw   = lrow & 7;          // swizzle key (mi/np-invariant)

    // Per-fragment row byte offsets (constant across iterations)
    uint32_t aRow[4], bRow[4];
#pragma unroll
    for (int i = 0; i < 4; i++) {
        aRow[i] = (warpM + i * 16 + lrow) * 128;
        bRow[i] = (warpN + i * 16 + lrow) * 128;
    }

    for (int it = 0; it < K_ITERS; it++) {
        CP_WAIT2();
        __syncthreads();

        const int st = it % STAGES;
        const uint32_t aBase = sbase + st * A_STAGE_BYTES;
        const uint32_t bBase = sbase + STAGES * A_STAGE_BYTES + st * B_STAGE_BYTES;

        uint32_t fa[2][4][4], fb[2][4][4];

        // Prefetch kt=0 fragments
        {
            const uint32_t off = (uint32_t)((lhalf ^ lsw) << 4);
#pragma unroll
            for (int i = 0; i < 4; i++) LDSM_X4(fa[0][i], aBase + aRow[i] + off);
#pragma unroll
            for (int i = 0; i < 4; i++) LDSM_X4(fb[0][i], bBase + bRow[i] + off);
        }

        // Issue next stage's cp.asyncs (drain under the MMA stream)
        int ld = it + STAGES - 1;
        if (ld < K_ITERS) stage_load(ld % STAGES, ld);
        CP_COMMIT();

#pragma unroll
        for (int kt = 0; kt < 4; kt++) {
            const int cur = kt & 1, nxt = cur ^ 1;
            if (kt < 3) {   // prefetch kt+1 fragments ahead of this kt's MMAs
                const uint32_t off = (uint32_t)((((kt + 1) * 2 + lhalf) ^ lsw) << 4);
#pragma unroll
                for (int i = 0; i < 4; i++) LDSM_X4(fa[nxt][i], aBase + aRow[i] + off);
#pragma unroll
                for (int i = 0; i < 4; i++) LDSM_X4(fb[nxt][i], bBase + bRow[i] + off);
            }
#pragma unroll
            for (int mi = 0; mi < 4; mi++)
#pragma unroll
                for (int ni = 0; ni < 8; ni++) {
                    const int np = ni >> 1, h = ni & 1;
                    MMA16816(acc[mi][ni], fa[cur][mi], fb[cur][np][h], fb[cur][np][2 + h]);
                }
        }
    }

    // Epilogue: direct fp32 stores (coalesced float2 per thread)
#pragma unroll
    for (int mi = 0; mi < 4; mi++) {
        int row = m0 + warpM + mi * 16 + (lid >> 2);
#pragma unroll
        for (int ni = 0; ni < 8; ni++) {
            int col = n0 + warpN + ni * 8 + (lid & 3) * 2;
            float2 v0 = make_float2(acc[mi][ni][0], acc[mi][ni][1]);
            float2 v1 = make_float2(acc[mi][ni][2], acc[mi][ni][3]);
            *reinterpret_cast<float2*>(C + (size_t)row * NN + col)       = v0;
            *reinterpret_cast<float2*>(C + (size_t)(row + 8) * NN + col) = v1;
        }
    }
}

// ---------------------------------------------------------------------------
// Host launch
// ---------------------------------------------------------------------------
extern "C" void kernel_launch(void* const* d_in, const int* in_sizes, int n_in,
                              void* d_out, int out_size) {
    const float* A  = (const float*)d_in[0];
    const int*   Bp = (const int*)d_in[1];
    const float* sc = (const float*)d_in[2];
    float* C = (float*)d_out;

    void* pAh = nullptr; void* pWh = nullptr;
    cudaGetSymbolAddress(&pAh, g_Ah);
    cudaGetSymbolAddress(&pWh, g_Wh);

    prep_a_kernel<<<(MM * (KK / 8)) / 256, 256>>>(A, (__half*)pAh);
    prep_w_kernel<<<dim3(NN / 256, (KK / 8) / 8), 256>>>(Bp, sc, (__half*)pWh);

    cudaFuncSetAttribute(gemm_kernel, cudaFuncAttributeMaxDynamicSharedMemorySize,
                         SMEM_BYTES);
    gemm_kernel<<<(MM / TM) * (NN / TN), 256, SMEM_BYTES>>>(
        (const __half*)pAh, (const __half*)pWh, C);
}